// round 1
// baseline (speedup 1.0000x reference)
#include <cuda_runtime.h>
#include <math.h>

// Problem dims
#define BB   128
#define NN   32
#define OBSD 128
#define AD   16
#define HH   4
#define DMD  128
#define ED   32
#define OAD  144
#define F1D  64
#define FIND 16
#define V0   (BB*NN*NN*FIND)   // weights start offset in d_out (value first, weights second)

// Scratch (device globals — no allocation allowed)
__device__ float g_aproj[BB*HH*NN*F1D];   // av_act @ W_f1_h   [B,H,N,64]
__device__ float g_dproj[BB*HH*NN*F1D];   // (av_pol-av_act) @ W_f1_h

__device__ __forceinline__ float lrelu(float x) { return x > 0.f ? x : 0.01f * x; }

// ---------------------------------------------------------------------------
// K1: per (b,h): se = leaky(states@W_se+b), k/q = se@W + b,
//     weights = softmax(q k^T / sqrt(128)) -> d_out tail
// smem floats: sT[128][36] | Wbuf[128][128] | seT[128][36] | kb[32][132] | qb[32][132] | sc[32][32]
// ---------------------------------------------------------------------------
#define K1_SMEM_F (4608 + 16384 + 4608 + 4224 + 4224 + 1024)

__global__ __launch_bounds__(256, 1)
void k1_attn(const float* __restrict__ states,
             const float* __restrict__ W_se, const float* __restrict__ b_se,
             const float* __restrict__ W_k,  const float* __restrict__ b_k,
             const float* __restrict__ W_q,  const float* __restrict__ b_q,
             float* __restrict__ out_w)
{
    const int h = blockIdx.x & 3;
    const int b = blockIdx.x >> 2;
    extern __shared__ float sm[];
    float* sT   = sm;           // [128][36] states transposed (o-major)
    float* Wbuf = sm + 4608;    // [128][128]
    float* seT  = sm + 20992;   // [128][36] se transposed (d-major)
    float* kb   = sm + 25600;   // [32][132]
    float* qb   = sm + 29824;   // [32][132]
    float* sc   = sm + 34048;   // [32][32]
    const int tid = threadIdx.x;

    // load states transposed
    const float* sb = states + b * NN * OBSD;
    for (int idx = tid; idx < NN * OBSD; idx += 256) {
        int n = idx >> 7, o = idx & 127;
        sT[o * 36 + n] = sb[idx];
    }
    { // load W_se[h]
        const float4* src = (const float4*)(W_se + (size_t)h * OBSD * DMD);
        float4* dst = (float4*)Wbuf;
        for (int idx = tid; idx < OBSD * DMD / 4; idx += 256) dst[idx] = src[idx];
    }
    __syncthreads();

    const int tr = tid >> 5;   // 0..7  -> rows 4*tr   (warp-uniform)
    const int tc = tid & 31;   // 0..31 -> cols 4*tc
    float acc[4][4];

    // ---- se = leaky(states @ W_se + b_se), store transposed ----
    #pragma unroll
    for (int r = 0; r < 4; r++)
        #pragma unroll
        for (int c = 0; c < 4; c++) acc[r][c] = 0.f;
    #pragma unroll 4
    for (int o = 0; o < OBSD; o++) {
        float4 a = *(const float4*)(sT + o * 36 + 4 * tr);       // broadcast per warp
        float4 w = *(const float4*)(Wbuf + o * DMD + 4 * tc);    // conflict-free
        float av[4] = {a.x, a.y, a.z, a.w};
        float wv[4] = {w.x, w.y, w.z, w.w};
        #pragma unroll
        for (int r = 0; r < 4; r++)
            #pragma unroll
            for (int c = 0; c < 4; c++) acc[r][c] += av[r] * wv[c];
    }
    {
        float4 bs = *(const float4*)(b_se + h * DMD + 4 * tc);
        float bb[4] = {bs.x, bs.y, bs.z, bs.w};
        #pragma unroll
        for (int c = 0; c < 4; c++) {
            int d = 4 * tc + c;
            #pragma unroll
            for (int r = 0; r < 4; r++)
                seT[d * 36 + 4 * tr + r] = lrelu(acc[r][c] + bb[c]);
        }
    }
    __syncthreads();
    { // load W_k[h]
        const float4* src = (const float4*)(W_k + (size_t)h * DMD * DMD);
        float4* dst = (float4*)Wbuf;
        for (int idx = tid; idx < DMD * DMD / 4; idx += 256) dst[idx] = src[idx];
    }
    __syncthreads();

    // ---- k = se @ W_k + b_k ----
    #pragma unroll
    for (int r = 0; r < 4; r++)
        #pragma unroll
        for (int c = 0; c < 4; c++) acc[r][c] = 0.f;
    #pragma unroll 4
    for (int d = 0; d < DMD; d++) {
        float4 a = *(const float4*)(seT + d * 36 + 4 * tr);
        float4 w = *(const float4*)(Wbuf + d * DMD + 4 * tc);
        float av[4] = {a.x, a.y, a.z, a.w};
        float wv[4] = {w.x, w.y, w.z, w.w};
        #pragma unroll
        for (int r = 0; r < 4; r++)
            #pragma unroll
            for (int c = 0; c < 4; c++) acc[r][c] += av[r] * wv[c];
    }
    {
        float4 bk4 = *(const float4*)(b_k + h * DMD + 4 * tc);
        #pragma unroll
        for (int r = 0; r < 4; r++) {
            float4 v = make_float4(acc[r][0] + bk4.x, acc[r][1] + bk4.y,
                                   acc[r][2] + bk4.z, acc[r][3] + bk4.w);
            *(float4*)(kb + (4 * tr + r) * 132 + 4 * tc) = v;
        }
    }
    __syncthreads();
    { // load W_q[h]
        const float4* src = (const float4*)(W_q + (size_t)h * DMD * DMD);
        float4* dst = (float4*)Wbuf;
        for (int idx = tid; idx < DMD * DMD / 4; idx += 256) dst[idx] = src[idx];
    }
    __syncthreads();

    // ---- q = se @ W_q + b_q ----
    #pragma unroll
    for (int r = 0; r < 4; r++)
        #pragma unroll
        for (int c = 0; c < 4; c++) acc[r][c] = 0.f;
    #pragma unroll 4
    for (int d = 0; d < DMD; d++) {
        float4 a = *(const float4*)(seT + d * 36 + 4 * tr);
        float4 w = *(const float4*)(Wbuf + d * DMD + 4 * tc);
        float av[4] = {a.x, a.y, a.z, a.w};
        float wv[4] = {w.x, w.y, w.z, w.w};
        #pragma unroll
        for (int r = 0; r < 4; r++)
            #pragma unroll
            for (int c = 0; c < 4; c++) acc[r][c] += av[r] * wv[c];
    }
    {
        float4 bq4 = *(const float4*)(b_q + h * DMD + 4 * tc);
        #pragma unroll
        for (int r = 0; r < 4; r++) {
            float4 v = make_float4(acc[r][0] + bq4.x, acc[r][1] + bq4.y,
                                   acc[r][2] + bq4.z, acc[r][3] + bq4.w);
            *(float4*)(qb + (4 * tr + r) * 132 + 4 * tc) = v;
        }
    }
    __syncthreads();

    // ---- scores = q k^T / sqrt(DM) ----
    {
        const int i  = tid >> 3;
        const int j0 = (tid & 7) * 4;
        float s4[4] = {0.f, 0.f, 0.f, 0.f};
        #pragma unroll 4
        for (int e = 0; e < DMD; e += 4) {
            float4 qv = *(const float4*)(qb + i * 132 + e);
            #pragma unroll
            for (int jj = 0; jj < 4; jj++) {
                float4 kv = *(const float4*)(kb + (j0 + jj) * 132 + e);
                s4[jj] += qv.x * kv.x + qv.y * kv.y + qv.z * kv.z + qv.w * kv.w;
            }
        }
        #pragma unroll
        for (int jj = 0; jj < 4; jj++)
            sc[i * 32 + j0 + jj] = s4[jj] * 0.08838834764831845f;  // 1/sqrt(128)
    }
    __syncthreads();

    // ---- softmax over j, write weights to d_out tail ----
    {
        const int lane = tid & 31, wp = tid >> 5;
        float* dst = out_w + ((size_t)(b * HH + h) * NN) * NN;
        #pragma unroll
        for (int rr = 0; rr < 4; rr++) {
            int i = wp * 4 + rr;
            float v = sc[i * 32 + lane];
            float m = v;
            #pragma unroll
            for (int off = 16; off > 0; off >>= 1)
                m = fmaxf(m, __shfl_xor_sync(0xffffffffu, m, off));
            float e = __expf(v - m);
            float s = e;
            #pragma unroll
            for (int off = 16; off > 0; off >>= 1)
                s += __shfl_xor_sync(0xffffffffu, s, off);
            dst[i * NN + lane] = e / s;
        }
    }
}

// ---------------------------------------------------------------------------
// K2: per (b,h): emb_{act,pol} = leaky(x@W_sap+b), av = leaky(emb@W_av+b),
//     Aproj = av_act@W_f1_h, Dproj = (av_pol-av_act)@W_f1_h
// smem floats: xT[144][68] | Wsap[144][128] | embT[128][68] | Wav[128][32] | avs[64][36] | wf1h[32][64]
// ---------------------------------------------------------------------------
#define K2_SMEM_F (9792 + 18432 + 8704 + 4096 + 2304 + 2048)

__global__ __launch_bounds__(256, 1)
void k2_sap(const float* __restrict__ states,
            const float* __restrict__ policies,
            const float* __restrict__ actions,
            const float* __restrict__ W_sap, const float* __restrict__ b_sap,
            const float* __restrict__ W_av,  const float* __restrict__ b_av,
            const float* __restrict__ W_f1)
{
    const int h = blockIdx.x & 3;
    const int b = blockIdx.x >> 2;
    extern __shared__ float sm[];
    float* xT   = sm;            // [144][68]  cols: 0..31 act rows, 32..63 pol rows
    float* Wsap = sm + 9792;     // [144][128]
    float* embT = sm + 28224;    // [128][68]
    float* Wav  = sm + 36928;    // [128][32]
    float* avs  = sm + 41024;    // [64][36]
    float* wf1h = sm + 43328;    // [32][64]
    const int tid = threadIdx.x;

    const float* sb = states + b * NN * OBSD;
    for (int idx = tid; idx < NN * OBSD; idx += 256) {
        int n = idx >> 7, o = idx & 127;
        float v = sb[idx];
        xT[o * 68 + n]      = v;   // act half (obs part identical)
        xT[o * 68 + 32 + n] = v;   // pol half
    }
    const float* ab = actions + b * NN * AD;
    const float* pb = policies + b * NN * AD;
    for (int idx = tid; idx < NN * AD; idx += 256) {
        int n = idx >> 4, c = idx & 15;
        xT[(OBSD + c) * 68 + n]      = ab[idx];
        xT[(OBSD + c) * 68 + 32 + n] = pb[idx];
    }
    {
        const float4* src = (const float4*)(W_sap + (size_t)h * OAD * DMD);
        float4* dst = (float4*)Wsap;
        for (int idx = tid; idx < OAD * DMD / 4; idx += 256) dst[idx] = src[idx];
    }
    {
        const float4* src = (const float4*)(W_av + (size_t)h * DMD * ED);
        float4* dst = (float4*)Wav;
        for (int idx = tid; idx < DMD * ED / 4; idx += 256) dst[idx] = src[idx];
    }
    {
        const float4* src = (const float4*)(W_f1 + (size_t)h * ED * F1D);
        float4* dst = (float4*)wf1h;
        for (int idx = tid; idx < ED * F1D / 4; idx += 256) dst[idx] = src[idx];
    }
    __syncthreads();

    const int tr = tid >> 4;  // 0..15 -> rows 4*tr (of 64)
    const int tc = tid & 15;  // 0..15 -> cols 8*tc (of 128)

    // ---- emb (64 x 128), 4x8 tiles ----
    {
        float acc[4][8];
        #pragma unroll
        for (int r = 0; r < 4; r++)
            #pragma unroll
            for (int c = 0; c < 8; c++) acc[r][c] = 0.f;
        #pragma unroll 2
        for (int cc = 0; cc < OAD; cc++) {
            float4 a  = *(const float4*)(xT + cc * 68 + 4 * tr);
            float4 w0 = *(const float4*)(Wsap + cc * DMD + 8 * tc);
            float4 w1 = *(const float4*)(Wsap + cc * DMD + 8 * tc + 4);
            float av[4] = {a.x, a.y, a.z, a.w};
            float wv[8] = {w0.x, w0.y, w0.z, w0.w, w1.x, w1.y, w1.z, w1.w};
            #pragma unroll
            for (int r = 0; r < 4; r++)
                #pragma unroll
                for (int c = 0; c < 8; c++) acc[r][c] += av[r] * wv[c];
        }
        float4 b0 = *(const float4*)(b_sap + h * DMD + 8 * tc);
        float4 b1 = *(const float4*)(b_sap + h * DMD + 8 * tc + 4);
        float bb[8] = {b0.x, b0.y, b0.z, b0.w, b1.x, b1.y, b1.z, b1.w};
        #pragma unroll
        for (int c = 0; c < 8; c++) {
            int d = 8 * tc + c;
            #pragma unroll
            for (int r = 0; r < 4; r++)
                embT[d * 68 + 4 * tr + r] = lrelu(acc[r][c] + bb[c]);
        }
    }
    __syncthreads();

    // ---- av (64 x 32), 4x2 tiles ----
    {
        float acc[4][2];
        #pragma unroll
        for (int r = 0; r < 4; r++) { acc[r][0] = 0.f; acc[r][1] = 0.f; }
        #pragma unroll 4
        for (int d = 0; d < DMD; d++) {
            float4 a = *(const float4*)(embT + d * 68 + 4 * tr);
            float2 w = *(const float2*)(Wav + d * ED + 2 * tc);
            float av[4] = {a.x, a.y, a.z, a.w};
            #pragma unroll
            for (int r = 0; r < 4; r++) {
                acc[r][0] += av[r] * w.x;
                acc[r][1] += av[r] * w.y;
            }
        }
        float2 bv = *(const float2*)(b_av + h * ED + 2 * tc);
        #pragma unroll
        for (int r = 0; r < 4; r++) {
            int m = 4 * tr + r;
            avs[m * 36 + 2 * tc]     = lrelu(acc[r][0] + bv.x);
            avs[m * 36 + 2 * tc + 1] = lrelu(acc[r][1] + bv.y);
        }
    }
    __syncthreads();

    // ---- Aproj / Dproj: [32][64] each ----
    {
        const int u  = tid & 63;
        const int i0 = tid >> 6;   // 0..3
        #pragma unroll
        for (int r = 0; r < 8; r++) {
            int j = i0 * 8 + r;
            float pa = 0.f, pd = 0.f;
            #pragma unroll 4
            for (int e = 0; e < ED; e++) {
                float aa = avs[j * 36 + e];               // warp-uniform broadcast
                float dd = avs[(32 + j) * 36 + e] - aa;
                float wv = wf1h[e * F1D + u];             // lane-consecutive
                pa += aa * wv;
                pd += dd * wv;
            }
            size_t o = ((size_t)(b * HH + h) * NN + j) * F1D + u;
            g_aproj[o] = pa;
            g_dproj[o] = pd;
        }
    }
}

// ---------------------------------------------------------------------------
// K3: per b: P[i] = b_f1 + sum_{h,k} w[h,i,k]*Aproj[h,k];
//     h1[i,j] = leaky(P[i] + sum_h w[h,i,j]*Dproj[h,j]); value = h1@W_f2 + b_f2
// smem floats: w4[4][32][32] | aproj[4][32][64] | dpT[4][64][32] | P[32][64] | wf2[64][16] | bf1[64] | bf2[16]
// ---------------------------------------------------------------------------
#define K3_SMEM_F (4096 + 8192 + 8192 + 2048 + 1024 + 64 + 16)

__global__ __launch_bounds__(256, 1)
void k3_final(const float* __restrict__ b_f1,
              const float* __restrict__ W_f2, const float* __restrict__ b_f2,
              const float* __restrict__ wgt,  // d_out + V0
              float* __restrict__ val)        // d_out
{
    const int b = blockIdx.x;
    extern __shared__ float sm[];
    float* w4    = sm;           // [4][32][32]
    float* aproj = sm + 4096;    // [4][32][64]
    float* dpT   = sm + 12288;   // [4][64][32]  (transposed: [h][u][j])
    float* P     = sm + 20480;   // [32][64]
    float* wf2   = sm + 22528;   // [64][16]
    float* bf1   = sm + 23552;   // [64]
    float* bf2   = sm + 23616;   // [16]
    const int tid = threadIdx.x;

    {
        const float4* src = (const float4*)(wgt + (size_t)b * 4096);
        float4* dst = (float4*)w4;
        for (int idx = tid; idx < 1024; idx += 256) dst[idx] = src[idx];
    }
    {
        const float4* src = (const float4*)(g_aproj + (size_t)b * 8192);
        float4* dst = (float4*)aproj;
        for (int idx = tid; idx < 2048; idx += 256) dst[idx] = src[idx];
    }
    {
        const float* dp = g_dproj + (size_t)b * 8192;
        for (int idx = tid; idx < 8192; idx += 256) {
            int hh = idx >> 11, j = (idx >> 6) & 31, u = idx & 63;
            dpT[(hh * 64 + u) * 32 + j] = dp[idx];
        }
    }
    for (int idx = tid; idx < 1024; idx += 256) wf2[idx] = W_f2[idx];
    if (tid < 64) bf1[tid] = b_f1[tid];
    if (tid < 16) bf2[tid] = b_f2[tid];
    __syncthreads();

    // ---- P[i][u] ----
    {
        const int u  = tid & 63;
        const int i0 = tid >> 6;   // 0..3 -> rows i0*8..i0*8+7
        float pacc[8];
        #pragma unroll
        for (int r = 0; r < 8; r++) pacc[r] = bf1[u];
        #pragma unroll 2
        for (int hk = 0; hk < 128; hk++) {
            int hh = hk >> 5, k = hk & 31;
            float av = aproj[(hh * 32 + k) * 64 + u];     // lane-consecutive
            #pragma unroll
            for (int r = 0; r < 8; r++)
                pacc[r] += w4[(hh * 32 + i0 * 8 + r) * 32 + k] * av;  // broadcast
        }
        #pragma unroll
        for (int r = 0; r < 8; r++) P[(i0 * 8 + r) * 64 + u] = pacc[r];
    }
    __syncthreads();

    // ---- fused per-(i,j) MLP ----
    for (int it = 0; it < 4; it++) {
        const int p = tid + 256 * it;
        const int i = p >> 5;        // warp-uniform
        const int j = p & 31;        // lane
        float wr0 = w4[(0 * 32 + i) * 32 + j];
        float wr1 = w4[(1 * 32 + i) * 32 + j];
        float wr2 = w4[(2 * 32 + i) * 32 + j];
        float wr3 = w4[(3 * 32 + i) * 32 + j];
        float h1[64];
        #pragma unroll
        for (int u = 0; u < 64; u++) {
            float t = P[i * 64 + u];
            t += wr0 * dpT[(0 * 64 + u) * 32 + j];
            t += wr1 * dpT[(1 * 64 + u) * 32 + j];
            t += wr2 * dpT[(2 * 64 + u) * 32 + j];
            t += wr3 * dpT[(3 * 64 + u) * 32 + j];
            h1[u] = lrelu(t);
        }
        float o[16];
        #pragma unroll
        for (int f = 0; f < 16; f++) o[f] = bf2[f];
        #pragma unroll
        for (int u = 0; u < 64; u++) {
            float hv = h1[u];
            float4 a = *(const float4*)(wf2 + u * 16 + 0);
            float4 bq = *(const float4*)(wf2 + u * 16 + 4);
            float4 c = *(const float4*)(wf2 + u * 16 + 8);
            float4 d = *(const float4*)(wf2 + u * 16 + 12);
            o[0]  += hv * a.x;  o[1]  += hv * a.y;  o[2]  += hv * a.z;  o[3]  += hv * a.w;
            o[4]  += hv * bq.x; o[5]  += hv * bq.y; o[6]  += hv * bq.z; o[7]  += hv * bq.w;
            o[8]  += hv * c.x;  o[9]  += hv * c.y;  o[10] += hv * c.z;  o[11] += hv * c.w;
            o[12] += hv * d.x;  o[13] += hv * d.y;  o[14] += hv * d.z;  o[15] += hv * d.w;
        }
        float* dst = val + (((size_t)b * NN + i) * NN + j) * FIND;
        *(float4*)(dst + 0)  = make_float4(o[0],  o[1],  o[2],  o[3]);
        *(float4*)(dst + 4)  = make_float4(o[4],  o[5],  o[6],  o[7]);
        *(float4*)(dst + 8)  = make_float4(o[8],  o[9],  o[10], o[11]);
        *(float4*)(dst + 12) = make_float4(o[12], o[13], o[14], o[15]);
    }
}

// ---------------------------------------------------------------------------
extern "C" void kernel_launch(void* const* d_in, const int* in_sizes, int n_in,
                              void* d_out, int out_size)
{
    (void)in_sizes; (void)n_in; (void)out_size;
    const float* states   = (const float*)d_in[0];
    const float* policies = (const float*)d_in[1];
    const float* actions  = (const float*)d_in[2];
    const float* W_se  = (const float*)d_in[3];  const float* b_se = (const float*)d_in[4];
    const float* W_k   = (const float*)d_in[5];  const float* b_k  = (const float*)d_in[6];
    const float* W_q   = (const float*)d_in[7];  const float* b_q  = (const float*)d_in[8];
    const float* W_sap = (const float*)d_in[9];  const float* b_sap= (const float*)d_in[10];
    const float* W_av  = (const float*)d_in[11]; const float* b_av = (const float*)d_in[12];
    const float* W_f1  = (const float*)d_in[13]; const float* b_f1 = (const float*)d_in[14];
    const float* W_f2  = (const float*)d_in[15]; const float* b_f2 = (const float*)d_in[16];
    float* out   = (float*)d_out;
    float* out_w = out + V0;

    cudaFuncSetAttribute(k1_attn,  cudaFuncAttributeMaxDynamicSharedMemorySize, K1_SMEM_F * 4);
    cudaFuncSetAttribute(k2_sap,   cudaFuncAttributeMaxDynamicSharedMemorySize, K2_SMEM_F * 4);
    cudaFuncSetAttribute(k3_final, cudaFuncAttributeMaxDynamicSharedMemorySize, K3_SMEM_F * 4);

    k1_attn<<<BB * HH, 256, K1_SMEM_F * 4>>>(states, W_se, b_se, W_k, b_k, W_q, b_q, out_w);
    k2_sap<<<BB * HH, 256, K2_SMEM_F * 4>>>(states, policies, actions,
                                            W_sap, b_sap, W_av, b_av, W_f1);
    k3_final<<<BB, 256, K3_SMEM_F * 4>>>(b_f1, W_f2, b_f2, out_w, out);
}

// round 2
// speedup vs baseline: 2.0324x; 2.0324x over previous
#include <cuda_runtime.h>
#include <math.h>

// Problem dims
#define BB   128
#define NN   32
#define OBSD 128
#define AD   16
#define HH   4
#define DMD  128
#define ED   32
#define OAD  144
#define F1D  64
#define FIND 16
#define V0   (BB*NN*NN*FIND)   // weights start offset in d_out (value first, weights second)

// Scratch (device globals — no allocation allowed)
__device__ float g_aproj[BB*HH*NN*F1D];   // av_act @ W_f1_h   [B,H,N,64]
__device__ float g_dproj[BB*HH*NN*F1D];   // (av_pol-av_act) @ W_f1_h

__device__ __forceinline__ float lrelu(float x) { return x > 0.f ? x : 0.01f * x; }

// ---------------------------------------------------------------------------
// k12: merged attention (role 0) + state-action-pair (role 1) kernel.
// Weights are NOT staged in smem — read via LDG (L2-resident, shared by all
// blocks). Only activations live in smem. 2 CTAs/SM.
//
// role 0 smem: sT[128][36] seT[128][36] kb[32][132] qb[32][132] sc[32][32]  (74.8KB)
// role 1 smem: xT[144][68] embT[128][68] avs[64][36] wf1h[32][64]           (91.4KB)
// ---------------------------------------------------------------------------
#define K12_SMEM_F (9792 + 8704 + 2304 + 2048)   // role-1 layout is the max

__global__ __launch_bounds__(256, 2)
void k12(const float* __restrict__ states,
         const float* __restrict__ policies,
         const float* __restrict__ actions,
         const float* __restrict__ W_se, const float* __restrict__ b_se,
         const float* __restrict__ W_k,  const float* __restrict__ b_k,
         const float* __restrict__ W_q,  const float* __restrict__ b_q,
         const float* __restrict__ W_sap, const float* __restrict__ b_sap,
         const float* __restrict__ W_av,  const float* __restrict__ b_av,
         const float* __restrict__ W_f1,
         float* __restrict__ out_w)
{
    extern __shared__ float sm[];
    const int tid  = threadIdx.x;
    const int role = blockIdx.x & 1;
    const int idx  = blockIdx.x >> 1;       // 0..511
    const int h    = idx & 3;
    const int b    = idx >> 2;

    if (role == 0) {
        // ================= K1: attention weights =================
        float* sT  = sm;            // [128][36]
        float* seT = sm + 4608;     // [128][36]
        float* kb  = sm + 9216;     // [32][132]
        float* qb  = sm + 13440;    // [32][132]
        float* sc  = sm + 17664;    // [32][32]

        const float* sb = states + b * NN * OBSD;
        for (int i = tid; i < NN * OBSD; i += 256) {
            int n = i >> 7, o = i & 127;
            sT[o * 36 + n] = sb[i];
        }
        __syncthreads();

        const int tr = tid >> 5;   // warp id: rows 4*tr
        const int tc = tid & 31;   // cols 4*tc

        // ---- se = leaky(states @ W_se + b_se) -> seT (d-major) ----
        {
            const float* Wh = W_se + (size_t)h * OBSD * DMD;
            float acc[4][4];
            #pragma unroll
            for (int r = 0; r < 4; r++)
                #pragma unroll
                for (int c = 0; c < 4; c++) acc[r][c] = 0.f;
            #pragma unroll 4
            for (int o = 0; o < OBSD; o++) {
                float4 a = *(const float4*)(sT + o * 36 + 4 * tr);
                float4 w = __ldg((const float4*)(Wh + o * DMD + 4 * tc));
                float av[4] = {a.x, a.y, a.z, a.w};
                float wv[4] = {w.x, w.y, w.z, w.w};
                #pragma unroll
                for (int r = 0; r < 4; r++)
                    #pragma unroll
                    for (int c = 0; c < 4; c++) acc[r][c] += av[r] * wv[c];
            }
            float4 bs = __ldg((const float4*)(b_se + h * DMD + 4 * tc));
            float bb4[4] = {bs.x, bs.y, bs.z, bs.w};
            #pragma unroll
            for (int c = 0; c < 4; c++) {
                int d = 4 * tc + c;
                #pragma unroll
                for (int r = 0; r < 4; r++)
                    seT[d * 36 + 4 * tr + r] = lrelu(acc[r][c] + bb4[c]);
            }
        }
        __syncthreads();

        // ---- k = se@W_k + b_k ; q = se@W_q + b_q  (single pass) ----
        {
            const float* Wkh = W_k + (size_t)h * DMD * DMD;
            const float* Wqh = W_q + (size_t)h * DMD * DMD;
            float ak[4][4], aq[4][4];
            #pragma unroll
            for (int r = 0; r < 4; r++)
                #pragma unroll
                for (int c = 0; c < 4; c++) { ak[r][c] = 0.f; aq[r][c] = 0.f; }
            #pragma unroll 4
            for (int d = 0; d < DMD; d++) {
                float4 a  = *(const float4*)(seT + d * 36 + 4 * tr);
                float4 wk = __ldg((const float4*)(Wkh + d * DMD + 4 * tc));
                float4 wq = __ldg((const float4*)(Wqh + d * DMD + 4 * tc));
                float av[4] = {a.x, a.y, a.z, a.w};
                float kv[4] = {wk.x, wk.y, wk.z, wk.w};
                float qv[4] = {wq.x, wq.y, wq.z, wq.w};
                #pragma unroll
                for (int r = 0; r < 4; r++)
                    #pragma unroll
                    for (int c = 0; c < 4; c++) {
                        ak[r][c] += av[r] * kv[c];
                        aq[r][c] += av[r] * qv[c];
                    }
            }
            float4 bk4 = __ldg((const float4*)(b_k + h * DMD + 4 * tc));
            float4 bq4 = __ldg((const float4*)(b_q + h * DMD + 4 * tc));
            #pragma unroll
            for (int r = 0; r < 4; r++) {
                *(float4*)(kb + (4 * tr + r) * 132 + 4 * tc) =
                    make_float4(ak[r][0] + bk4.x, ak[r][1] + bk4.y,
                                ak[r][2] + bk4.z, ak[r][3] + bk4.w);
                *(float4*)(qb + (4 * tr + r) * 132 + 4 * tc) =
                    make_float4(aq[r][0] + bq4.x, aq[r][1] + bq4.y,
                                aq[r][2] + bq4.z, aq[r][3] + bq4.w);
            }
        }
        __syncthreads();

        // ---- scores = q k^T / sqrt(DM) ----
        {
            const int i  = tid >> 3;
            const int j0 = (tid & 7) * 4;
            float s4[4] = {0.f, 0.f, 0.f, 0.f};
            #pragma unroll 4
            for (int e = 0; e < DMD; e += 4) {
                float4 qv = *(const float4*)(qb + i * 132 + e);
                #pragma unroll
                for (int jj = 0; jj < 4; jj++) {
                    float4 kv = *(const float4*)(kb + (j0 + jj) * 132 + e);
                    s4[jj] += qv.x * kv.x + qv.y * kv.y + qv.z * kv.z + qv.w * kv.w;
                }
            }
            #pragma unroll
            for (int jj = 0; jj < 4; jj++)
                sc[i * 32 + j0 + jj] = s4[jj] * 0.08838834764831845f;
        }
        __syncthreads();

        // ---- softmax over j -> d_out tail ----
        {
            const int lane = tid & 31, wp = tid >> 5;
            float* dst = out_w + ((size_t)(b * HH + h) * NN) * NN;
            #pragma unroll
            for (int rr = 0; rr < 4; rr++) {
                int i = wp * 4 + rr;
                float v = sc[i * 32 + lane];
                float m = v;
                #pragma unroll
                for (int off = 16; off > 0; off >>= 1)
                    m = fmaxf(m, __shfl_xor_sync(0xffffffffu, m, off));
                float e = __expf(v - m);
                float s = e;
                #pragma unroll
                for (int off = 16; off > 0; off >>= 1)
                    s += __shfl_xor_sync(0xffffffffu, s, off);
                dst[i * NN + lane] = e / s;
            }
        }
    } else {
        // ================= K2: sap embeddings -> Aproj/Dproj =================
        float* xT   = sm;            // [144][68] cols 0..31 act, 32..63 pol
        float* embT = sm + 9792;     // [128][68]
        float* avs  = sm + 18496;    // [64][36]
        float* wf1h = sm + 20800;    // [32][64]

        const float* sb = states + b * NN * OBSD;
        for (int i = tid; i < NN * OBSD; i += 256) {
            int n = i >> 7, o = i & 127;
            float v = sb[i];
            xT[o * 68 + n]      = v;
            xT[o * 68 + 32 + n] = v;
        }
        const float* ab = actions  + b * NN * AD;
        const float* pb = policies + b * NN * AD;
        for (int i = tid; i < NN * AD; i += 256) {
            int n = i >> 4, c = i & 15;
            xT[(OBSD + c) * 68 + n]      = ab[i];
            xT[(OBSD + c) * 68 + 32 + n] = pb[i];
        }
        {
            const float4* src = (const float4*)(W_f1 + (size_t)h * ED * F1D);
            float4* dst = (float4*)wf1h;
            for (int i = tid; i < ED * F1D / 4; i += 256) dst[i] = src[i];
        }
        __syncthreads();

        const int tr = tid >> 4;  // 0..15 -> rows 4*tr (of 64)
        const int tc = tid & 15;  // 0..15 -> cols 8*tc (of 128)

        // ---- emb (64 x 128) ----
        {
            const float* Wh = W_sap + (size_t)h * OAD * DMD;
            float acc[4][8];
            #pragma unroll
            for (int r = 0; r < 4; r++)
                #pragma unroll
                for (int c = 0; c < 8; c++) acc[r][c] = 0.f;
            #pragma unroll 2
            for (int cc = 0; cc < OAD; cc++) {
                float4 a  = *(const float4*)(xT + cc * 68 + 4 * tr);
                float4 w0 = __ldg((const float4*)(Wh + cc * DMD + 8 * tc));
                float4 w1 = __ldg((const float4*)(Wh + cc * DMD + 8 * tc + 4));
                float av[4] = {a.x, a.y, a.z, a.w};
                float wv[8] = {w0.x, w0.y, w0.z, w0.w, w1.x, w1.y, w1.z, w1.w};
                #pragma unroll
                for (int r = 0; r < 4; r++)
                    #pragma unroll
                    for (int c = 0; c < 8; c++) acc[r][c] += av[r] * wv[c];
            }
            float4 b0 = __ldg((const float4*)(b_sap + h * DMD + 8 * tc));
            float4 b1 = __ldg((const float4*)(b_sap + h * DMD + 8 * tc + 4));
            float bb8[8] = {b0.x, b0.y, b0.z, b0.w, b1.x, b1.y, b1.z, b1.w};
            #pragma unroll
            for (int c = 0; c < 8; c++) {
                int d = 8 * tc + c;
                #pragma unroll
                for (int r = 0; r < 4; r++)
                    embT[d * 68 + 4 * tr + r] = lrelu(acc[r][c] + bb8[c]);
            }
        }
        __syncthreads();

        // ---- av (64 x 32) ----
        {
            const float* Wh = W_av + (size_t)h * DMD * ED;
            float acc[4][2];
            #pragma unroll
            for (int r = 0; r < 4; r++) { acc[r][0] = 0.f; acc[r][1] = 0.f; }
            #pragma unroll 4
            for (int d = 0; d < DMD; d++) {
                float4 a = *(const float4*)(embT + d * 68 + 4 * tr);
                float2 w = __ldg((const float2*)(Wh + d * ED + 2 * tc));
                float av[4] = {a.x, a.y, a.z, a.w};
                #pragma unroll
                for (int r = 0; r < 4; r++) {
                    acc[r][0] += av[r] * w.x;
                    acc[r][1] += av[r] * w.y;
                }
            }
            float2 bv = __ldg((const float2*)(b_av + h * ED + 2 * tc));
            #pragma unroll
            for (int r = 0; r < 4; r++) {
                int m = 4 * tr + r;
                avs[m * 36 + 2 * tc]     = lrelu(acc[r][0] + bv.x);
                avs[m * 36 + 2 * tc + 1] = lrelu(acc[r][1] + bv.y);
            }
        }
        __syncthreads();

        // ---- Aproj / Dproj: [32][64] each ----
        {
            const int u  = tid & 63;
            const int i0 = tid >> 6;
            #pragma unroll
            for (int r = 0; r < 8; r++) {
                int j = i0 * 8 + r;
                float pa = 0.f, pd = 0.f;
                #pragma unroll 4
                for (int e = 0; e < ED; e++) {
                    float aa = avs[j * 36 + e];
                    float dd = avs[(32 + j) * 36 + e] - aa;
                    float wv = wf1h[e * F1D + u];
                    pa += aa * wv;
                    pd += dd * wv;
                }
                size_t o = ((size_t)(b * HH + h) * NN + j) * F1D + u;
                g_aproj[o] = pa;
                g_dproj[o] = pd;
            }
        }
    }
}

// ---------------------------------------------------------------------------
// K3: grid = 2*B; block (b, half) handles i-rows [half*16, half*16+16).
// P[i] = b_f1 + sum_{h,k} w[h,i,k]*Aproj[h,k];
// h1[i,j] = leaky(P[i] + sum_h w[h,i,j]*Dproj[h,j]); value = h1@W_f2 + b_f2
// smem: w4h[4][16][32] | aproj[4][32][64] | dpT[4][64][33] | P[16][64] | wf2[64][16] | bf1 | bf2
// ---------------------------------------------------------------------------
#define K3_SMEM_F (2048 + 8192 + 8448 + 1024 + 1024 + 64 + 16)

__global__ __launch_bounds__(256, 2)
void k3_final(const float* __restrict__ b_f1,
              const float* __restrict__ W_f2, const float* __restrict__ b_f2,
              const float* __restrict__ wgt,  // d_out + V0
              float* __restrict__ val)        // d_out
{
    const int half   = blockIdx.x & 1;
    const int b      = blockIdx.x >> 1;
    const int base_i = half * 16;
    extern __shared__ float sm[];
    float* w4h   = sm;           // [4][16][32]
    float* aproj = sm + 2048;    // [4][32][64]
    float* dpT   = sm + 10240;   // [4][64][33]
    float* P     = sm + 18688;   // [16][64]
    float* wf2   = sm + 19712;   // [64][16]
    float* bf1   = sm + 20736;   // [64]
    float* bf2   = sm + 20800;   // [16]
    const int tid = threadIdx.x;

    {   // weights rows for our 16 i per head
        const float* wg = wgt + (size_t)b * 4096;
        for (int i = tid; i < 2048 / 4; i += 256) {
            int e4 = i * 4;                     // element index into w4h
            int hh = e4 >> 9, rem = e4 & 511;   // rem = il*32 + k
            int il = rem >> 5, k = rem & 31;
            *(float4*)(w4h + e4) =
                *(const float4*)(wg + ((size_t)hh * 32 + base_i + il) * 32 + k);
        }
    }
    {
        const float4* src = (const float4*)(g_aproj + (size_t)b * 8192);
        float4* dst = (float4*)aproj;
        for (int i = tid; i < 2048; i += 256) dst[i] = src[i];
    }
    {
        const float* dp = g_dproj + (size_t)b * 8192;
        for (int i = tid; i < 8192; i += 256) {
            int hh = i >> 11, j = (i >> 6) & 31, u = i & 63;
            dpT[(hh * 64 + u) * 33 + j] = dp[i];
        }
    }
    for (int i = tid; i < 1024; i += 256) wf2[i] = W_f2[i];
    if (tid < 64) bf1[tid] = b_f1[tid];
    if (tid < 16) bf2[tid] = b_f2[tid];
    __syncthreads();

    // ---- P[il][u] for 16 local rows ----
    {
        const int u  = tid & 63;
        const int i0 = tid >> 6;   // 0..3 -> local rows i0*4..i0*4+3
        float pacc[4];
        #pragma unroll
        for (int r = 0; r < 4; r++) pacc[r] = bf1[u];
        #pragma unroll 2
        for (int hk = 0; hk < 128; hk++) {
            int hh = hk >> 5, k = hk & 31;
            float av = aproj[(hh * 32 + k) * 64 + u];
            #pragma unroll
            for (int r = 0; r < 4; r++)
                pacc[r] += w4h[hh * 512 + (i0 * 4 + r) * 32 + k] * av;
        }
        #pragma unroll
        for (int r = 0; r < 4; r++) P[(i0 * 4 + r) * 64 + u] = pacc[r];
    }
    __syncthreads();

    // ---- fused per-(i,j) MLP: 16*32 = 512 pairs, 2 per thread ----
    #pragma unroll
    for (int it = 0; it < 2; it++) {
        const int p  = tid + 256 * it;
        const int il = p >> 5;       // local i, warp-uniform
        const int j  = p & 31;       // lane
        float wr0 = w4h[0 * 512 + il * 32 + j];
        float wr1 = w4h[1 * 512 + il * 32 + j];
        float wr2 = w4h[2 * 512 + il * 32 + j];
        float wr3 = w4h[3 * 512 + il * 32 + j];
        float h1[64];
        #pragma unroll
        for (int u = 0; u < 64; u++) {
            float t = P[il * 64 + u];
            t += wr0 * dpT[(0 * 64 + u) * 33 + j];
            t += wr1 * dpT[(1 * 64 + u) * 33 + j];
            t += wr2 * dpT[(2 * 64 + u) * 33 + j];
            t += wr3 * dpT[(3 * 64 + u) * 33 + j];
            h1[u] = lrelu(t);
        }
        float o[16];
        #pragma unroll
        for (int f = 0; f < 16; f++) o[f] = bf2[f];
        #pragma unroll
        for (int u = 0; u < 64; u++) {
            float hv = h1[u];
            float4 a = *(const float4*)(wf2 + u * 16 + 0);
            float4 c4 = *(const float4*)(wf2 + u * 16 + 4);
            float4 c8 = *(const float4*)(wf2 + u * 16 + 8);
            float4 cc = *(const float4*)(wf2 + u * 16 + 12);
            o[0]  += hv * a.x;  o[1]  += hv * a.y;  o[2]  += hv * a.z;  o[3]  += hv * a.w;
            o[4]  += hv * c4.x; o[5]  += hv * c4.y; o[6]  += hv * c4.z; o[7]  += hv * c4.w;
            o[8]  += hv * c8.x; o[9]  += hv * c8.y; o[10] += hv * c8.z; o[11] += hv * c8.w;
            o[12] += hv * cc.x; o[13] += hv * cc.y; o[14] += hv * cc.z; o[15] += hv * cc.w;
        }
        float* dst = val + (((size_t)b * NN + base_i + il) * NN + j) * FIND;
        *(float4*)(dst + 0)  = make_float4(o[0],  o[1],  o[2],  o[3]);
        *(float4*)(dst + 4)  = make_float4(o[4],  o[5],  o[6],  o[7]);
        *(float4*)(dst + 8)  = make_float4(o[8],  o[9],  o[10], o[11]);
        *(float4*)(dst + 12) = make_float4(o[12], o[13], o[14], o[15]);
    }
}

// ---------------------------------------------------------------------------
extern "C" void kernel_launch(void* const* d_in, const int* in_sizes, int n_in,
                              void* d_out, int out_size)
{
    (void)in_sizes; (void)n_in; (void)out_size;
    const float* states   = (const float*)d_in[0];
    const float* policies = (const float*)d_in[1];
    const float* actions  = (const float*)d_in[2];
    const float* W_se  = (const float*)d_in[3];  const float* b_se = (const float*)d_in[4];
    const float* W_k   = (const float*)d_in[5];  const float* b_k  = (const float*)d_in[6];
    const float* W_q   = (const float*)d_in[7];  const float* b_q  = (const float*)d_in[8];
    const float* W_sap = (const float*)d_in[9];  const float* b_sap= (const float*)d_in[10];
    const float* W_av  = (const float*)d_in[11]; const float* b_av = (const float*)d_in[12];
    const float* W_f1  = (const float*)d_in[13]; const float* b_f1 = (const float*)d_in[14];
    const float* W_f2  = (const float*)d_in[15]; const float* b_f2 = (const float*)d_in[16];
    float* out   = (float*)d_out;
    float* out_w = out + V0;

    cudaFuncSetAttribute(k12,      cudaFuncAttributeMaxDynamicSharedMemorySize, K12_SMEM_F * 4);
    cudaFuncSetAttribute(k3_final, cudaFuncAttributeMaxDynamicSharedMemorySize, K3_SMEM_F * 4);

    k12<<<BB * HH * 2, 256, K12_SMEM_F * 4>>>(states, policies, actions,
                                              W_se, b_se, W_k, b_k, W_q, b_q,
                                              W_sap, b_sap, W_av, b_av, W_f1, out_w);
    k3_final<<<BB * 2, 256, K3_SMEM_F * 4>>>(b_f1, W_f2, b_f2, out_w, out);
}

// round 3
// speedup vs baseline: 3.2453x; 1.5968x over previous
#include <cuda_runtime.h>
#include <math.h>

// Problem dims
#define BB   128
#define NN   32
#define OBSD 128
#define AD   16
#define HH   4
#define DMD  128
#define ED   32
#define OAD  144
#define F1D  64
#define FIND 16
#define V0   (BB*NN*NN*FIND)   // weights start offset in d_out (value first, weights second)

// Scratch (device globals — no allocation allowed)
__device__ float g_aproj[BB*HH*NN*F1D];   // av_act @ W_f1_h   [B,H,N,64]
__device__ float g_dproj[BB*HH*NN*F1D];   // (av_pol-av_act) @ W_f1_h

__device__ __forceinline__ float lrelu(float x) { return x > 0.f ? x : 0.01f * x; }

// ---------------------------------------------------------------------------
// k12: merged attention (role 0) + state-action-pair (role 1) kernel.
// Weights read via LDG (L2-resident, shared by all blocks); activations in smem.
// Targeting 3 CTAs/SM:
//   role 0: sT[128][36] seT[128][36] kb[32][132] qb[32][132] sc[32][32] = 74.75KB
//   role 1: xT[144][68] embT[128][68] = 74.0KB  (avs aliases xT; wf1h aliases embT)
// ---------------------------------------------------------------------------
#define K12_SMEM_F (4608 + 4608 + 4224 + 4224 + 1024)   // 18688 floats = 74.75KB

__global__ __launch_bounds__(256, 3)
void k12(const float* __restrict__ states,
         const float* __restrict__ policies,
         const float* __restrict__ actions,
         const float* __restrict__ W_se, const float* __restrict__ b_se,
         const float* __restrict__ W_k,  const float* __restrict__ b_k,
         const float* __restrict__ W_q,  const float* __restrict__ b_q,
         const float* __restrict__ W_sap, const float* __restrict__ b_sap,
         const float* __restrict__ W_av,  const float* __restrict__ b_av,
         const float* __restrict__ W_f1,
         float* __restrict__ out_w)
{
    extern __shared__ float sm[];
    const int tid  = threadIdx.x;
    const int role = blockIdx.x & 1;
    const int idx  = blockIdx.x >> 1;       // 0..511
    const int h    = idx & 3;
    const int b    = idx >> 2;

    if (role == 0) {
        // ================= K1: attention weights =================
        float* sT  = sm;            // [128][36]
        float* seT = sm + 4608;     // [128][36]
        float* kb  = sm + 9216;     // [32][132]
        float* qb  = sm + 13440;    // [32][132]
        float* sc  = sm + 17664;    // [32][32]

        const float* sb = states + b * NN * OBSD;
        for (int i = tid; i < NN * OBSD; i += 256) {
            int n = i >> 7, o = i & 127;
            sT[o * 36 + n] = sb[i];
        }
        __syncthreads();

        const int tr = tid >> 5;   // warp id: rows 4*tr
        const int tc = tid & 31;   // cols 4*tc

        // ---- se = leaky(states @ W_se + b_se) -> seT (d-major) ----
        {
            const float* Wh = W_se + (size_t)h * OBSD * DMD;
            float acc[4][4];
            #pragma unroll
            for (int r = 0; r < 4; r++)
                #pragma unroll
                for (int c = 0; c < 4; c++) acc[r][c] = 0.f;
            #pragma unroll 4
            for (int o = 0; o < OBSD; o++) {
                float4 a = *(const float4*)(sT + o * 36 + 4 * tr);
                float4 w = __ldg((const float4*)(Wh + o * DMD + 4 * tc));
                float av[4] = {a.x, a.y, a.z, a.w};
                float wv[4] = {w.x, w.y, w.z, w.w};
                #pragma unroll
                for (int r = 0; r < 4; r++)
                    #pragma unroll
                    for (int c = 0; c < 4; c++) acc[r][c] += av[r] * wv[c];
            }
            float4 bs = __ldg((const float4*)(b_se + h * DMD + 4 * tc));
            float bb4[4] = {bs.x, bs.y, bs.z, bs.w};
            #pragma unroll
            for (int c = 0; c < 4; c++) {
                int d = 4 * tc + c;
                #pragma unroll
                for (int r = 0; r < 4; r++)
                    seT[d * 36 + 4 * tr + r] = lrelu(acc[r][c] + bb4[c]);
            }
        }
        __syncthreads();

        // ---- k = se@W_k + b_k ; q = se@W_q + b_q  (single pass, unroll 2) ----
        {
            const float* Wkh = W_k + (size_t)h * DMD * DMD;
            const float* Wqh = W_q + (size_t)h * DMD * DMD;
            float ak[4][4], aq[4][4];
            #pragma unroll
            for (int r = 0; r < 4; r++)
                #pragma unroll
                for (int c = 0; c < 4; c++) { ak[r][c] = 0.f; aq[r][c] = 0.f; }
            #pragma unroll 2
            for (int d = 0; d < DMD; d++) {
                float4 a  = *(const float4*)(seT + d * 36 + 4 * tr);
                float4 wk = __ldg((const float4*)(Wkh + d * DMD + 4 * tc));
                float4 wq = __ldg((const float4*)(Wqh + d * DMD + 4 * tc));
                float av[4] = {a.x, a.y, a.z, a.w};
                float kv[4] = {wk.x, wk.y, wk.z, wk.w};
                float qv[4] = {wq.x, wq.y, wq.z, wq.w};
                #pragma unroll
                for (int r = 0; r < 4; r++)
                    #pragma unroll
                    for (int c = 0; c < 4; c++) {
                        ak[r][c] += av[r] * kv[c];
                        aq[r][c] += av[r] * qv[c];
                    }
            }
            float4 bk4 = __ldg((const float4*)(b_k + h * DMD + 4 * tc));
            float4 bq4 = __ldg((const float4*)(b_q + h * DMD + 4 * tc));
            #pragma unroll
            for (int r = 0; r < 4; r++) {
                *(float4*)(kb + (4 * tr + r) * 132 + 4 * tc) =
                    make_float4(ak[r][0] + bk4.x, ak[r][1] + bk4.y,
                                ak[r][2] + bk4.z, ak[r][3] + bk4.w);
                *(float4*)(qb + (4 * tr + r) * 132 + 4 * tc) =
                    make_float4(aq[r][0] + bq4.x, aq[r][1] + bq4.y,
                                aq[r][2] + bq4.z, aq[r][3] + bq4.w);
            }
        }
        __syncthreads();

        // ---- scores = q k^T / sqrt(DM) ----
        {
            const int i  = tid >> 3;
            const int j0 = (tid & 7) * 4;
            float s4[4] = {0.f, 0.f, 0.f, 0.f};
            #pragma unroll 4
            for (int e = 0; e < DMD; e += 4) {
                float4 qv = *(const float4*)(qb + i * 132 + e);
                #pragma unroll
                for (int jj = 0; jj < 4; jj++) {
                    float4 kv = *(const float4*)(kb + (j0 + jj) * 132 + e);
                    s4[jj] += qv.x * kv.x + qv.y * kv.y + qv.z * kv.z + qv.w * kv.w;
                }
            }
            #pragma unroll
            for (int jj = 0; jj < 4; jj++)
                sc[i * 32 + j0 + jj] = s4[jj] * 0.08838834764831845f;
        }
        __syncthreads();

        // ---- softmax over j -> d_out tail ----
        {
            const int lane = tid & 31, wp = tid >> 5;
            float* dst = out_w + ((size_t)(b * HH + h) * NN) * NN;
            #pragma unroll
            for (int rr = 0; rr < 4; rr++) {
                int i = wp * 4 + rr;
                float v = sc[i * 32 + lane];
                float m = v;
                #pragma unroll
                for (int off = 16; off > 0; off >>= 1)
                    m = fmaxf(m, __shfl_xor_sync(0xffffffffu, m, off));
                float e = __expf(v - m);
                float s = e;
                #pragma unroll
                for (int off = 16; off > 0; off >>= 1)
                    s += __shfl_xor_sync(0xffffffffu, s, off);
                dst[i * NN + lane] = e / s;
            }
        }
    } else {
        // ================= K2: sap embeddings -> Aproj/Dproj =================
        float* xT   = sm;            // [144][68] cols 0..31 act, 32..63 pol
        float* embT = sm + 9792;     // [128][68]
        float* avs  = sm;            // [64][36]  (aliases xT after emb phase)
        float* wf1h = sm + 9792;     // [32][64]  (aliases embT after av phase)

        const float* sb = states + b * NN * OBSD;
        for (int i = tid; i < NN * OBSD; i += 256) {
            int n = i >> 7, o = i & 127;
            float v = sb[i];
            xT[o * 68 + n]      = v;
            xT[o * 68 + 32 + n] = v;
        }
        const float* ab = actions  + b * NN * AD;
        const float* pb = policies + b * NN * AD;
        for (int i = tid; i < NN * AD; i += 256) {
            int n = i >> 4, c = i & 15;
            xT[(OBSD + c) * 68 + n]      = ab[i];
            xT[(OBSD + c) * 68 + 32 + n] = pb[i];
        }
        __syncthreads();

        const int tr = tid >> 4;  // 0..15 -> rows 4*tr (of 64)
        const int tc = tid & 15;  // 0..15 -> cols 8*tc (of 128)

        // ---- emb (64 x 128) ----
        {
            const float* Wh = W_sap + (size_t)h * OAD * DMD;
            float acc[4][8];
            #pragma unroll
            for (int r = 0; r < 4; r++)
                #pragma unroll
                for (int c = 0; c < 8; c++) acc[r][c] = 0.f;
            #pragma unroll 2
            for (int cc = 0; cc < OAD; cc++) {
                float4 a  = *(const float4*)(xT + cc * 68 + 4 * tr);
                float4 w0 = __ldg((const float4*)(Wh + cc * DMD + 8 * tc));
                float4 w1 = __ldg((const float4*)(Wh + cc * DMD + 8 * tc + 4));
                float av[4] = {a.x, a.y, a.z, a.w};
                float wv[8] = {w0.x, w0.y, w0.z, w0.w, w1.x, w1.y, w1.z, w1.w};
                #pragma unroll
                for (int r = 0; r < 4; r++)
                    #pragma unroll
                    for (int c = 0; c < 8; c++) acc[r][c] += av[r] * wv[c];
            }
            float4 b0 = __ldg((const float4*)(b_sap + h * DMD + 8 * tc));
            float4 b1 = __ldg((const float4*)(b_sap + h * DMD + 8 * tc + 4));
            float bb8[8] = {b0.x, b0.y, b0.z, b0.w, b1.x, b1.y, b1.z, b1.w};
            #pragma unroll
            for (int c = 0; c < 8; c++) {
                int d = 8 * tc + c;
                #pragma unroll
                for (int r = 0; r < 4; r++)
                    embT[d * 68 + 4 * tr + r] = lrelu(acc[r][c] + bb8[c]);
            }
        }
        __syncthreads();

        // ---- av (64 x 32) -> avs (aliases xT; xT is dead now) ----
        {
            const float* Wh = W_av + (size_t)h * DMD * ED;
            float acc[4][2];
            #pragma unroll
            for (int r = 0; r < 4; r++) { acc[r][0] = 0.f; acc[r][1] = 0.f; }
            #pragma unroll 4
            for (int d = 0; d < DMD; d++) {
                float4 a = *(const float4*)(embT + d * 68 + 4 * tr);
                float2 w = __ldg((const float2*)(Wh + d * ED + 2 * tc));
                float av[4] = {a.x, a.y, a.z, a.w};
                #pragma unroll
                for (int r = 0; r < 4; r++) {
                    acc[r][0] += av[r] * w.x;
                    acc[r][1] += av[r] * w.y;
                }
            }
            float2 bv = __ldg((const float2*)(b_av + h * ED + 2 * tc));
            #pragma unroll
            for (int r = 0; r < 4; r++) {
                int m = 4 * tr + r;
                avs[m * 36 + 2 * tc]     = lrelu(acc[r][0] + bv.x);
                avs[m * 36 + 2 * tc + 1] = lrelu(acc[r][1] + bv.y);
            }
        }
        __syncthreads();   // embT reads done -> safe to overwrite with wf1h

        {
            const float4* src = (const float4*)(W_f1 + (size_t)h * ED * F1D);
            float4* dst = (float4*)wf1h;
            for (int i = tid; i < ED * F1D / 4; i += 256) dst[i] = src[i];
        }
        __syncthreads();

        // ---- Aproj / Dproj: [32][64] each ----
        {
            const int u  = tid & 63;
            const int i0 = tid >> 6;
            #pragma unroll
            for (int r = 0; r < 8; r++) {
                int j = i0 * 8 + r;
                float pa = 0.f, pd = 0.f;
                #pragma unroll 4
                for (int e = 0; e < ED; e++) {
                    float aa = avs[j * 36 + e];
                    float dd = avs[(32 + j) * 36 + e] - aa;
                    float wv = wf1h[e * F1D + u];
                    pa += aa * wv;
                    pd += dd * wv;
                }
                size_t o = ((size_t)(b * HH + h) * NN + j) * F1D + u;
                g_aproj[o] = pa;
                g_dproj[o] = pd;
            }
        }
    }
}

// ---------------------------------------------------------------------------
// K3: grid = 2*B; block (b, half) handles i-rows [half*16, half*16+16).
// P[i] = b_f1 + sum_{h,k} w[h,i,k]*Aproj[h,k];
// h1[i,j,u] = leaky(P[i,u] + sum_h w[h,i,j]*Dproj[h,j,u]); value = h1@W_f2 + b_f2
// The u-loop is fully fused (h1 never materialized) -> no register spills.
// ---------------------------------------------------------------------------
#define K3_SMEM_F (2048 + 8192 + 8448 + 1024 + 1024 + 64 + 16)

__global__ __launch_bounds__(256, 2)
void k3_final(const float* __restrict__ b_f1,
              const float* __restrict__ W_f2, const float* __restrict__ b_f2,
              const float* __restrict__ wgt,  // d_out + V0
              float* __restrict__ val)        // d_out
{
    const int half   = blockIdx.x & 1;
    const int b      = blockIdx.x >> 1;
    const int base_i = half * 16;
    extern __shared__ float sm[];
    float* w4h   = sm;           // [4][16][32]
    float* aproj = sm + 2048;    // [4][32][64]
    float* dpT   = sm + 10240;   // [4][64][33]
    float* P     = sm + 18688;   // [16][64]
    float* wf2   = sm + 19712;   // [64][16]
    float* bf1   = sm + 20736;   // [64]
    float* bf2   = sm + 20800;   // [16]
    const int tid = threadIdx.x;

    {   // weights rows for our 16 i per head
        const float* wg = wgt + (size_t)b * 4096;
        for (int i = tid; i < 2048 / 4; i += 256) {
            int e4 = i * 4;                     // element index into w4h
            int hh = e4 >> 9, rem = e4 & 511;   // rem = il*32 + k
            int il = rem >> 5, k = rem & 31;
            *(float4*)(w4h + e4) =
                *(const float4*)(wg + ((size_t)hh * 32 + base_i + il) * 32 + k);
        }
    }
    {
        const float4* src = (const float4*)(g_aproj + (size_t)b * 8192);
        float4* dst = (float4*)aproj;
        for (int i = tid; i < 2048; i += 256) dst[i] = src[i];
    }
    {
        const float* dp = g_dproj + (size_t)b * 8192;
        for (int i = tid; i < 8192; i += 256) {
            int hh = i >> 11, j = (i >> 6) & 31, u = i & 63;
            dpT[(hh * 64 + u) * 33 + j] = dp[i];
        }
    }
    for (int i = tid; i < 1024; i += 256) wf2[i] = W_f2[i];
    if (tid < 64) bf1[tid] = b_f1[tid];
    if (tid < 16) bf2[tid] = b_f2[tid];
    __syncthreads();

    // ---- P[il][u] for 16 local rows ----
    {
        const int u  = tid & 63;
        const int i0 = tid >> 6;   // 0..3 -> local rows i0*4..i0*4+3
        float pacc[4];
        #pragma unroll
        for (int r = 0; r < 4; r++) pacc[r] = bf1[u];
        #pragma unroll 2
        for (int hk = 0; hk < 128; hk++) {
            int hh = hk >> 5, k = hk & 31;
            float av = aproj[(hh * 32 + k) * 64 + u];
            #pragma unroll
            for (int r = 0; r < 4; r++)
                pacc[r] += w4h[hh * 512 + (i0 * 4 + r) * 32 + k] * av;
        }
        #pragma unroll
        for (int r = 0; r < 4; r++) P[(i0 * 4 + r) * 64 + u] = pacc[r];
    }
    __syncthreads();

    // ---- fused per-(i,j) MLP: 16*32 = 512 pairs, 2 per thread ----
    #pragma unroll
    for (int it = 0; it < 2; it++) {
        const int p  = tid + 256 * it;
        const int il = p >> 5;       // local i, warp-uniform
        const int j  = p & 31;       // lane
        float wr0 = w4h[0 * 512 + il * 32 + j];
        float wr1 = w4h[1 * 512 + il * 32 + j];
        float wr2 = w4h[2 * 512 + il * 32 + j];
        float wr3 = w4h[3 * 512 + il * 32 + j];
        float o[16];
        #pragma unroll
        for (int f = 0; f < 16; f++) o[f] = bf2[f];
        #pragma unroll 8
        for (int u = 0; u < 64; u++) {
            float t = P[il * 64 + u];
            t += wr0 * dpT[(0 * 64 + u) * 33 + j];
            t += wr1 * dpT[(1 * 64 + u) * 33 + j];
            t += wr2 * dpT[(2 * 64 + u) * 33 + j];
            t += wr3 * dpT[(3 * 64 + u) * 33 + j];
            float hv = lrelu(t);
            float4 a  = *(const float4*)(wf2 + u * 16 + 0);
            float4 c4 = *(const float4*)(wf2 + u * 16 + 4);
            float4 c8 = *(const float4*)(wf2 + u * 16 + 8);
            float4 cc = *(const float4*)(wf2 + u * 16 + 12);
            o[0]  += hv * a.x;  o[1]  += hv * a.y;  o[2]  += hv * a.z;  o[3]  += hv * a.w;
            o[4]  += hv * c4.x; o[5]  += hv * c4.y; o[6]  += hv * c4.z; o[7]  += hv * c4.w;
            o[8]  += hv * c8.x; o[9]  += hv * c8.y; o[10] += hv * c8.z; o[11] += hv * c8.w;
            o[12] += hv * cc.x; o[13] += hv * cc.y; o[14] += hv * cc.z; o[15] += hv * cc.w;
        }
        float* dst = val + (((size_t)b * NN + base_i + il) * NN + j) * FIND;
        *(float4*)(dst + 0)  = make_float4(o[0],  o[1],  o[2],  o[3]);
        *(float4*)(dst + 4)  = make_float4(o[4],  o[5],  o[6],  o[7]);
        *(float4*)(dst + 8)  = make_float4(o[8],  o[9],  o[10], o[11]);
        *(float4*)(dst + 12) = make_float4(o[12], o[13], o[14], o[15]);
    }
}

// ---------------------------------------------------------------------------
extern "C" void kernel_launch(void* const* d_in, const int* in_sizes, int n_in,
                              void* d_out, int out_size)
{
    (void)in_sizes; (void)n_in; (void)out_size;
    const float* states   = (const float*)d_in[0];
    const float* policies = (const float*)d_in[1];
    const float* actions  = (const float*)d_in[2];
    const float* W_se  = (const float*)d_in[3];  const float* b_se = (const float*)d_in[4];
    const float* W_k   = (const float*)d_in[5];  const float* b_k  = (const float*)d_in[6];
    const float* W_q   = (const float*)d_in[7];  const float* b_q  = (const float*)d_in[8];
    const float* W_sap = (const float*)d_in[9];  const float* b_sap= (const float*)d_in[10];
    const float* W_av  = (const float*)d_in[11]; const float* b_av = (const float*)d_in[12];
    const float* W_f1  = (const float*)d_in[13]; const float* b_f1 = (const float*)d_in[14];
    const float* W_f2  = (const float*)d_in[15]; const float* b_f2 = (const float*)d_in[16];
    float* out   = (float*)d_out;
    float* out_w = out + V0;

    cudaFuncSetAttribute(k12,      cudaFuncAttributeMaxDynamicSharedMemorySize, K12_SMEM_F * 4);
    cudaFuncSetAttribute(k3_final, cudaFuncAttributeMaxDynamicSharedMemorySize, K3_SMEM_F * 4);

    k12<<<BB * HH * 2, 256, K12_SMEM_F * 4>>>(states, policies, actions,
                                              W_se, b_se, W_k, b_k, W_q, b_q,
                                              W_sap, b_sap, W_av, b_av, W_f1, out_w);
    k3_final<<<BB * 2, 256, K3_SMEM_F * 4>>>(b_f1, W_f2, b_f2, out_w, out);
}

// round 4
// speedup vs baseline: 3.7606x; 1.1588x over previous
#include <cuda_runtime.h>
#include <math.h>

// Problem dims
#define BB   128
#define NN   32
#define OBSD 128
#define AD   16
#define HH   4
#define DMD  128
#define ED   32
#define OAD  144
#define F1D  64
#define FIND 16
#define V0   (BB*NN*NN*FIND)   // weights start offset in d_out (value first, weights second)

// Scratch (device globals — no allocation allowed)
__device__ float g_aproj[BB*HH*NN*F1D];   // av_act @ W_f1_h
__device__ float g_dproj[BB*HH*NN*F1D];   // (av_pol-av_act) @ W_f1_h
__device__ float g_M [HH*DMD*DMD];        // W_q W_k^T per head
__device__ float g_v2[HH*DMD];            // W_k b_q per head

__device__ __forceinline__ float lrelu(float x) { return x > 0.f ? x : 0.01f * x; }

// ---------------------------------------------------------------------------
// k0: precompute M_h = W_q W_k^T  and v2_h = W_k b_q.
// grid = 16: (h, chunk) with chunk = 32 columns (d') of M.
// smem: WqT[128][132] transposed (e-major) + WkTc[128][36]
// ---------------------------------------------------------------------------
#define K0_SMEM_F (128*132 + 128*36)

__global__ __launch_bounds__(256)
void k0_prep(const float* __restrict__ W_q, const float* __restrict__ W_k,
             const float* __restrict__ b_q)
{
    const int h     = blockIdx.x >> 2;
    const int chunk = blockIdx.x & 3;
    extern __shared__ float sm[];
    float* WqT  = sm;              // [e][d] stride 132
    float* WkTc = sm + 128*132;    // [e][d'loc] stride 36
    const int tid = threadIdx.x;

    const float* Wq = W_q + (size_t)h * DMD * DMD;
    for (int i = tid; i < DMD * DMD; i += 256) {
        int d = i >> 7, e = i & 127;
        WqT[e * 132 + d] = Wq[i];
    }
    const float* Wk = W_k + (size_t)h * DMD * DMD + (size_t)chunk * 32 * DMD;
    for (int i = tid; i < 32 * DMD; i += 256) {
        int dl = i >> 7, e = i & 127;
        WkTc[e * 36 + dl] = Wk[i];
    }
    __syncthreads();

    const int dgrp = tid >> 3;   // 0..31 -> d rows 4*dgrp
    const int cgrp = tid & 7;    // 0..7  -> d'loc cols 4*cgrp
    float acc[4][4];
    #pragma unroll
    for (int r = 0; r < 4; r++)
        #pragma unroll
        for (int c = 0; c < 4; c++) acc[r][c] = 0.f;
    #pragma unroll 4
    for (int e = 0; e < DMD; e++) {
        float4 a = *(const float4*)(WqT + e * 132 + 4 * dgrp);
        float4 b = *(const float4*)(WkTc + e * 36 + 4 * cgrp);
        float av[4] = {a.x, a.y, a.z, a.w};
        float bv[4] = {b.x, b.y, b.z, b.w};
        #pragma unroll
        for (int r = 0; r < 4; r++)
            #pragma unroll
            for (int c = 0; c < 4; c++) acc[r][c] += av[r] * bv[c];
    }
    float* Mdst = g_M + (size_t)h * DMD * DMD;
    #pragma unroll
    for (int r = 0; r < 4; r++)
        *(float4*)(Mdst + (size_t)(4 * dgrp + r) * DMD + chunk * 32 + 4 * cgrp) =
            make_float4(acc[r][0], acc[r][1], acc[r][2], acc[r][3]);

    if (tid < 32) {
        const float* bq = b_q + h * DMD;
        float s = 0.f;
        #pragma unroll 4
        for (int e = 0; e < DMD; e++) s += WkTc[e * 36 + tid] * bq[e];
        g_v2[h * DMD + chunk * 32 + tid] = s;
    }
}

// ---------------------------------------------------------------------------
// k12: merged attention (role 0) + state-action-pair (role 1) kernel.
// role 0: se=leaky(states@W_se+b); t=se@M_h; scores_ij=(t_i.se_j+v2.se_j)/sqrt(DM)
//         weights=softmax(scores) -> d_out tail.  (bias cross-terms that are
//         constant per softmax row are dropped — mathematically identical)
// role 1: sp=states@W_sap[0:128]; emb_{act,pol}=leaky(sp+{act,pol}@W_sap[128:]+b)
//         av=leaky(emb@W_av+b); Aproj/Dproj=... @W_f1_h -> global scratch
// smem (shared budget): role0 18720 floats, role1 14464 floats -> 74.9KB, 3 CTAs/SM
// ---------------------------------------------------------------------------
#define K12_SMEM_F (18720)

__global__ __launch_bounds__(256, 3)
void k12(const float* __restrict__ states,
         const float* __restrict__ policies,
         const float* __restrict__ actions,
         const float* __restrict__ W_se, const float* __restrict__ b_se,
         const float* __restrict__ W_sap, const float* __restrict__ b_sap,
         const float* __restrict__ W_av,  const float* __restrict__ b_av,
         const float* __restrict__ W_f1,
         float* __restrict__ out_w)
{
    extern __shared__ float sm[];
    const int tid  = threadIdx.x;
    const int role = blockIdx.x & 1;
    const int idx  = blockIdx.x >> 1;       // 0..511
    const int h    = idx & 3;
    const int b    = idx >> 2;

    if (role == 0) {
        // ================= attention weights =================
        float* sT  = sm;            // [128][36]  states o-major
        float* seT = sm + 4608;     // [128][36]  se d-major
        float* seR = sm + 9216;     // [32][132]  se row-major
        float* tb  = sm + 13440;    // [32][132]  t = se@M row-major
        float* sc  = sm + 17664;    // [32][32]
        float* rv  = sm + 18688;    // [32]

        const float* sb = states + b * NN * OBSD;
        for (int i = tid; i < NN * OBSD; i += 256) {
            int n = i >> 7, o = i & 127;
            sT[o * 36 + n] = sb[i];
        }
        __syncthreads();

        const int tr = tid >> 5;   // rows 4*tr
        const int tc = tid & 31;   // cols 4*tc

        // ---- se = leaky(states @ W_se + b_se) -> seT (d-major) + seR (row) ----
        {
            const float* Wh = W_se + (size_t)h * OBSD * DMD;
            float acc[4][4];
            #pragma unroll
            for (int r = 0; r < 4; r++)
                #pragma unroll
                for (int c = 0; c < 4; c++) acc[r][c] = 0.f;
            #pragma unroll 4
            for (int o = 0; o < OBSD; o++) {
                float4 a = *(const float4*)(sT + o * 36 + 4 * tr);
                float4 w = __ldg((const float4*)(Wh + o * DMD + 4 * tc));
                float av[4] = {a.x, a.y, a.z, a.w};
                float wv[4] = {w.x, w.y, w.z, w.w};
                #pragma unroll
                for (int r = 0; r < 4; r++)
                    #pragma unroll
                    for (int c = 0; c < 4; c++) acc[r][c] += av[r] * wv[c];
            }
            float4 bs = __ldg((const float4*)(b_se + h * DMD + 4 * tc));
            float bb4[4] = {bs.x, bs.y, bs.z, bs.w};
            #pragma unroll
            for (int c = 0; c < 4; c++) {
                int d = 4 * tc + c;
                #pragma unroll
                for (int r = 0; r < 4; r++) {
                    float v = lrelu(acc[r][c] + bb4[c]);
                    seT[d * 36 + 4 * tr + r] = v;
                    seR[(4 * tr + r) * 132 + d] = v;
                }
            }
        }
        __syncthreads();

        // ---- t = se @ M_h  (no bias) ----
        {
            const float* Mh = g_M + (size_t)h * DMD * DMD;
            float acc[4][4];
            #pragma unroll
            for (int r = 0; r < 4; r++)
                #pragma unroll
                for (int c = 0; c < 4; c++) acc[r][c] = 0.f;
            #pragma unroll 4
            for (int d = 0; d < DMD; d++) {
                float4 a = *(const float4*)(seT + d * 36 + 4 * tr);
                float4 w = __ldg((const float4*)(Mh + (size_t)d * DMD + 4 * tc));
                float av[4] = {a.x, a.y, a.z, a.w};
                float wv[4] = {w.x, w.y, w.z, w.w};
                #pragma unroll
                for (int r = 0; r < 4; r++)
                    #pragma unroll
                    for (int c = 0; c < 4; c++) acc[r][c] += av[r] * wv[c];
            }
            #pragma unroll
            for (int r = 0; r < 4; r++)
                *(float4*)(tb + (4 * tr + r) * 132 + 4 * tc) =
                    make_float4(acc[r][0], acc[r][1], acc[r][2], acc[r][3]);
        }
        // ---- rv[j] = v2 . se_j  (threads 0..127; seR ready since first sync) ----
        if (tid < 128) {
            const int j = tid >> 2, part = tid & 3;
            const float* v2 = g_v2 + h * DMD;
            float s = 0.f;
            #pragma unroll 8
            for (int e = part * 32; e < part * 32 + 32; e++)
                s += v2[e] * seR[j * 132 + e];
            s += __shfl_xor_sync(0xffffffffu, s, 1);
            s += __shfl_xor_sync(0xffffffffu, s, 2);
            if (part == 0) rv[j] = s;
        }
        __syncthreads();

        // ---- scores_ij = (t_i . se_j + rv_j) / sqrt(DM) ----
        {
            const int i  = tid >> 3;
            const int j0 = (tid & 7) * 4;
            float s4[4] = {0.f, 0.f, 0.f, 0.f};
            #pragma unroll 4
            for (int e = 0; e < DMD; e += 4) {
                float4 qv = *(const float4*)(tb + i * 132 + e);
                #pragma unroll
                for (int jj = 0; jj < 4; jj++) {
                    float4 kv = *(const float4*)(seR + (j0 + jj) * 132 + e);
                    s4[jj] += qv.x * kv.x + qv.y * kv.y + qv.z * kv.z + qv.w * kv.w;
                }
            }
            #pragma unroll
            for (int jj = 0; jj < 4; jj++)
                sc[i * 32 + j0 + jj] = (s4[jj] + rv[j0 + jj]) * 0.08838834764831845f;
        }
        __syncthreads();

        // ---- softmax over j -> d_out tail ----
        {
            const int lane = tid & 31, wp = tid >> 5;
            float* dst = out_w + ((size_t)(b * HH + h) * NN) * NN;
            #pragma unroll
            for (int rr = 0; rr < 4; rr++) {
                int i = wp * 4 + rr;
                float v = sc[i * 32 + lane];
                float m = v;
                #pragma unroll
                for (int off = 16; off > 0; off >>= 1)
                    m = fmaxf(m, __shfl_xor_sync(0xffffffffu, m, off));
                float e = __expf(v - m);
                float s = e;
                #pragma unroll
                for (int off = 16; off > 0; off >>= 1)
                    s += __shfl_xor_sync(0xffffffffu, s, off);
                dst[i * NN + lane] = e / s;
            }
        }
    } else {
        // ================= sap embeddings -> Aproj/Dproj =================
        float* sT   = sm;            // [128][36]
        float* aT   = sm + 4608;     // [16][36]
        float* pT   = sm + 5184;     // [16][36]
        float* embT = sm + 5760;     // [128][68] cols 0..31 act, 32..63 pol
        float* avs  = sm;            // [64][36]  (aliases sT after emb phase)
        float* wf1h = sm + 5760;     // [32][64]  (aliases embT after av phase)

        const float* sb = states + b * NN * OBSD;
        for (int i = tid; i < NN * OBSD; i += 256) {
            int n = i >> 7, o = i & 127;
            sT[o * 36 + n] = sb[i];
        }
        const float* ab = actions  + b * NN * AD;
        const float* pb = policies + b * NN * AD;
        for (int i = tid; i < NN * AD; i += 256) {
            int n = i >> 4, c = i & 15;
            aT[c * 36 + n] = ab[i];
            pT[c * 36 + n] = pb[i];
        }
        __syncthreads();

        const int tr = tid >> 5;  // rows 4*tr of 32
        const int tc = tid & 31;  // cols 4*tc of 128

        // ---- sp = states @ W_sap[0:128]; emb = leaky(sp + tail + b) ----
        {
            const float* Wh = W_sap + (size_t)h * OAD * DMD;
            float acc[4][4];
            #pragma unroll
            for (int r = 0; r < 4; r++)
                #pragma unroll
                for (int c = 0; c < 4; c++) acc[r][c] = 0.f;
            #pragma unroll 4
            for (int o = 0; o < OBSD; o++) {
                float4 a = *(const float4*)(sT + o * 36 + 4 * tr);
                float4 w = __ldg((const float4*)(Wh + o * DMD + 4 * tc));
                float av[4] = {a.x, a.y, a.z, a.w};
                float wv[4] = {w.x, w.y, w.z, w.w};
                #pragma unroll
                for (int r = 0; r < 4; r++)
                    #pragma unroll
                    for (int c = 0; c < 4; c++) acc[r][c] += av[r] * wv[c];
            }
            float4 bs = __ldg((const float4*)(b_sap + h * DMD + 4 * tc));
            float bb4[4] = {bs.x, bs.y, bs.z, bs.w};

            // action tail + store
            {
                float accA[4][4];
                #pragma unroll
                for (int r = 0; r < 4; r++)
                    #pragma unroll
                    for (int c = 0; c < 4; c++) accA[r][c] = acc[r][c];
                #pragma unroll 4
                for (int c16 = 0; c16 < AD; c16++) {
                    float4 a = *(const float4*)(aT + c16 * 36 + 4 * tr);
                    float4 w = __ldg((const float4*)(Wh + (size_t)(OBSD + c16) * DMD + 4 * tc));
                    float av[4] = {a.x, a.y, a.z, a.w};
                    float wv[4] = {w.x, w.y, w.z, w.w};
                    #pragma unroll
                    for (int r = 0; r < 4; r++)
                        #pragma unroll
                        for (int c = 0; c < 4; c++) accA[r][c] += av[r] * wv[c];
                }
                #pragma unroll
                for (int c = 0; c < 4; c++) {
                    int d = 4 * tc + c;
                    #pragma unroll
                    for (int r = 0; r < 4; r++)
                        embT[d * 68 + 4 * tr + r] = lrelu(accA[r][c] + bb4[c]);
                }
            }
            // policy tail + store
            {
                float accP[4][4];
                #pragma unroll
                for (int r = 0; r < 4; r++)
                    #pragma unroll
                    for (int c = 0; c < 4; c++) accP[r][c] = acc[r][c];
                #pragma unroll 4
                for (int c16 = 0; c16 < AD; c16++) {
                    float4 a = *(const float4*)(pT + c16 * 36 + 4 * tr);
                    float4 w = __ldg((const float4*)(Wh + (size_t)(OBSD + c16) * DMD + 4 * tc));
                    float av[4] = {a.x, a.y, a.z, a.w};
                    float wv[4] = {w.x, w.y, w.z, w.w};
                    #pragma unroll
                    for (int r = 0; r < 4; r++)
                        #pragma unroll
                        for (int c = 0; c < 4; c++) accP[r][c] += av[r] * wv[c];
                }
                #pragma unroll
                for (int c = 0; c < 4; c++) {
                    int d = 4 * tc + c;
                    #pragma unroll
                    for (int r = 0; r < 4; r++)
                        embT[d * 68 + 32 + 4 * tr + r] = lrelu(accP[r][c] + bb4[c]);
                }
            }
        }
        __syncthreads();

        // ---- av (64 x 32) -> avs (aliases sT/aT/pT region; dead now) ----
        {
            const int tr2 = tid >> 4;  // 0..15 -> rows 4*tr2 of 64
            const int tc2 = tid & 15;  // 0..15 -> cols 2*tc2 of 32
            const float* Wh = W_av + (size_t)h * DMD * ED;
            float acc[4][2];
            #pragma unroll
            for (int r = 0; r < 4; r++) { acc[r][0] = 0.f; acc[r][1] = 0.f; }
            #pragma unroll 4
            for (int d = 0; d < DMD; d++) {
                float4 a = *(const float4*)(embT + d * 68 + 4 * tr2);
                float2 w = __ldg((const float2*)(Wh + d * ED + 2 * tc2));
                float av[4] = {a.x, a.y, a.z, a.w};
                #pragma unroll
                for (int r = 0; r < 4; r++) {
                    acc[r][0] += av[r] * w.x;
                    acc[r][1] += av[r] * w.y;
                }
            }
            float2 bv = __ldg((const float2*)(b_av + h * ED + 2 * tc2));
            #pragma unroll
            for (int r = 0; r < 4; r++) {
                int m = 4 * tr2 + r;
                avs[m * 36 + 2 * tc2]     = lrelu(acc[r][0] + bv.x);
                avs[m * 36 + 2 * tc2 + 1] = lrelu(acc[r][1] + bv.y);
            }
        }
        __syncthreads();   // embT reads done -> safe to overwrite with wf1h

        {
            const float4* src = (const float4*)(W_f1 + (size_t)h * ED * F1D);
            float4* dst = (float4*)wf1h;
            for (int i = tid; i < ED * F1D / 4; i += 256) dst[i] = src[i];
        }
        __syncthreads();

        // ---- Aproj / Dproj: [32][64] each ----
        {
            const int u  = tid & 63;
            const int i0 = tid >> 6;
            #pragma unroll
            for (int r = 0; r < 8; r++) {
                int j = i0 * 8 + r;
                float pa = 0.f, pd = 0.f;
                #pragma unroll 4
                for (int e = 0; e < ED; e++) {
                    float aa = avs[j * 36 + e];
                    float dd = avs[(32 + j) * 36 + e] - aa;
                    float wv = wf1h[e * F1D + u];
                    pa += aa * wv;
                    pd += dd * wv;
                }
                size_t o = ((size_t)(b * HH + h) * NN + j) * F1D + u;
                g_aproj[o] = pa;
                g_dproj[o] = pd;
            }
        }
    }
}

// ---------------------------------------------------------------------------
// K3: grid = 2*B; block (b, half) handles i-rows [half*16, half*16+16).
// ---------------------------------------------------------------------------
#define K3_SMEM_F (2048 + 8192 + 8448 + 1024 + 1024 + 64 + 16)

__global__ __launch_bounds__(256, 2)
void k3_final(const float* __restrict__ b_f1,
              const float* __restrict__ W_f2, const float* __restrict__ b_f2,
              const float* __restrict__ wgt,  // d_out + V0
              float* __restrict__ val)        // d_out
{
    const int half   = blockIdx.x & 1;
    const int b      = blockIdx.x >> 1;
    const int base_i = half * 16;
    extern __shared__ float sm[];
    float* w4h   = sm;           // [4][16][32]
    float* aproj = sm + 2048;    // [4][32][64]
    float* dpT   = sm + 10240;   // [4][64][33]
    float* P     = sm + 18688;   // [16][64]
    float* wf2   = sm + 19712;   // [64][16]
    float* bf1   = sm + 20736;   // [64]
    float* bf2   = sm + 20800;   // [16]
    const int tid = threadIdx.x;

    {
        const float* wg = wgt + (size_t)b * 4096;
        for (int i = tid; i < 2048 / 4; i += 256) {
            int e4 = i * 4;
            int hh = e4 >> 9, rem = e4 & 511;
            int il = rem >> 5, k = rem & 31;
            *(float4*)(w4h + e4) =
                *(const float4*)(wg + ((size_t)hh * 32 + base_i + il) * 32 + k);
        }
    }
    {
        const float4* src = (const float4*)(g_aproj + (size_t)b * 8192);
        float4* dst = (float4*)aproj;
        for (int i = tid; i < 2048; i += 256) dst[i] = src[i];
    }
    {
        const float* dp = g_dproj + (size_t)b * 8192;
        for (int i = tid; i < 8192; i += 256) {
            int hh = i >> 11, j = (i >> 6) & 31, u = i & 63;
            dpT[(hh * 64 + u) * 33 + j] = dp[i];
        }
    }
    for (int i = tid; i < 1024; i += 256) wf2[i] = W_f2[i];
    if (tid < 64) bf1[tid] = b_f1[tid];
    if (tid < 16) bf2[tid] = b_f2[tid];
    __syncthreads();

    // ---- P[il][u] ----
    {
        const int u  = tid & 63;
        const int i0 = tid >> 6;
        float pacc[4];
        #pragma unroll
        for (int r = 0; r < 4; r++) pacc[r] = bf1[u];
        #pragma unroll 2
        for (int hk = 0; hk < 128; hk++) {
            int hh = hk >> 5, k = hk & 31;
            float av = aproj[(hh * 32 + k) * 64 + u];
            #pragma unroll
            for (int r = 0; r < 4; r++)
                pacc[r] += w4h[hh * 512 + (i0 * 4 + r) * 32 + k] * av;
        }
        #pragma unroll
        for (int r = 0; r < 4; r++) P[(i0 * 4 + r) * 64 + u] = pacc[r];
    }
    __syncthreads();

    // ---- fused per-(i,j) MLP ----
    #pragma unroll
    for (int it = 0; it < 2; it++) {
        const int p  = tid + 256 * it;
        const int il = p >> 5;
        const int j  = p & 31;
        float wr0 = w4h[0 * 512 + il * 32 + j];
        float wr1 = w4h[1 * 512 + il * 32 + j];
        float wr2 = w4h[2 * 512 + il * 32 + j];
        float wr3 = w4h[3 * 512 + il * 32 + j];
        float o[16];
        #pragma unroll
        for (int f = 0; f < 16; f++) o[f] = bf2[f];
        #pragma unroll 8
        for (int u = 0; u < 64; u++) {
            float t = P[il * 64 + u];
            t += wr0 * dpT[(0 * 64 + u) * 33 + j];
            t += wr1 * dpT[(1 * 64 + u) * 33 + j];
            t += wr2 * dpT[(2 * 64 + u) * 33 + j];
            t += wr3 * dpT[(3 * 64 + u) * 33 + j];
            float hv = lrelu(t);
            float4 a  = *(const float4*)(wf2 + u * 16 + 0);
            float4 c4 = *(const float4*)(wf2 + u * 16 + 4);
            float4 c8 = *(const float4*)(wf2 + u * 16 + 8);
            float4 cc = *(const float4*)(wf2 + u * 16 + 12);
            o[0]  += hv * a.x;  o[1]  += hv * a.y;  o[2]  += hv * a.z;  o[3]  += hv * a.w;
            o[4]  += hv * c4.x; o[5]  += hv * c4.y; o[6]  += hv * c4.z; o[7]  += hv * c4.w;
            o[8]  += hv * c8.x; o[9]  += hv * c8.y; o[10] += hv * c8.z; o[11] += hv * c8.w;
            o[12] += hv * cc.x; o[13] += hv * cc.y; o[14] += hv * cc.z; o[15] += hv * cc.w;
        }
        float* dst = val + (((size_t)b * NN + base_i + il) * NN + j) * FIND;
        *(float4*)(dst + 0)  = make_float4(o[0],  o[1],  o[2],  o[3]);
        *(float4*)(dst + 4)  = make_float4(o[4],  o[5],  o[6],  o[7]);
        *(float4*)(dst + 8)  = make_float4(o[8],  o[9],  o[10], o[11]);
        *(float4*)(dst + 12) = make_float4(o[12], o[13], o[14], o[15]);
    }
}

// ---------------------------------------------------------------------------
extern "C" void kernel_launch(void* const* d_in, const int* in_sizes, int n_in,
                              void* d_out, int out_size)
{
    (void)in_sizes; (void)n_in; (void)out_size;
    const float* states   = (const float*)d_in[0];
    const float* policies = (const float*)d_in[1];
    const float* actions  = (const float*)d_in[2];
    const float* W_se  = (const float*)d_in[3];  const float* b_se = (const float*)d_in[4];
    const float* W_k   = (const float*)d_in[5];  const float* b_k  = (const float*)d_in[6];
    const float* W_q   = (const float*)d_in[7];  const float* b_q  = (const float*)d_in[8];
    const float* W_sap = (const float*)d_in[9];  const float* b_sap= (const float*)d_in[10];
    const float* W_av  = (const float*)d_in[11]; const float* b_av = (const float*)d_in[12];
    const float* W_f1  = (const float*)d_in[13]; const float* b_f1 = (const float*)d_in[14];
    const float* W_f2  = (const float*)d_in[15]; const float* b_f2 = (const float*)d_in[16];
    (void)b_k;
    float* out   = (float*)d_out;
    float* out_w = out + V0;

    cudaFuncSetAttribute(k0_prep,  cudaFuncAttributeMaxDynamicSharedMemorySize, K0_SMEM_F * 4);
    cudaFuncSetAttribute(k12,      cudaFuncAttributeMaxDynamicSharedMemorySize, K12_SMEM_F * 4);
    cudaFuncSetAttribute(k3_final, cudaFuncAttributeMaxDynamicSharedMemorySize, K3_SMEM_F * 4);

    k0_prep<<<16, 256, K0_SMEM_F * 4>>>(W_q, W_k, b_q);
    k12<<<BB * HH * 2, 256, K12_SMEM_F * 4>>>(states, policies, actions,
                                              W_se, b_se,
                                              W_sap, b_sap, W_av, b_av, W_f1, out_w);
    k3_final<<<BB * 2, 256, K3_SMEM_F * 4>>>(b_f1, W_f2, b_f2, out_w, out);
}